// round 12
// baseline (speedup 1.0000x reference)
#include <cuda_runtime.h>
#include <cuda_bf16.h>
#include <cstdint>

#define M_DIM 4096
#define N_DIM 1024
#define K_DIM 1024
#define NUM_OPS 8

#define BM 128
#define BN 128
#define BK 32
#define NSTEPS (K_DIM / BK)   // 32
#define NSTAGE 2

// pitched rows: 40 bf16 = 80B = 5x16B (odd multiple -> conflict-free ldmatrix)
#define PITCH 40
#define TILE_BYTES (128 * PITCH * 2)          // 10240 (128 rows x 32 k)
#define STAGE_BYTES (4 * TILE_BYTES)          // Ah, Al, Bh, Bl = 40960
#define SMEM_TOTAL (NSTAGE * STAGE_BYTES)     // 81920 -> 2 CTAs/SM fits 227KB

// ---- device scratch (pre-converted split operands) ----
__device__ __nv_bfloat16 g_Ah[M_DIM * K_DIM];   // [M][K]
__device__ __nv_bfloat16 g_Al[M_DIM * K_DIM];
__device__ __nv_bfloat16 g_Bh[N_DIM * K_DIM];   // [N][K] (W transposed)
__device__ __nv_bfloat16 g_Bl[N_DIM * K_DIM];

// ---------------- helpers ----------------
__device__ __forceinline__ uint32_t bf2_bits(__nv_bfloat162 h) {
    return *reinterpret_cast<uint32_t*>(&h);
}
__device__ __forceinline__ void split1(float v, __nv_bfloat16& hi, __nv_bfloat16& lo) {
    hi = __float2bfloat16_rn(v);
    lo = __float2bfloat16_rn(v - __bfloat162float(hi));
}
__device__ __forceinline__ void split4(float4 v, uint2& hi, uint2& lo) {
    __nv_bfloat162 h01 = __floats2bfloat162_rn(v.x, v.y);
    __nv_bfloat162 h23 = __floats2bfloat162_rn(v.z, v.w);
    float r0 = v.x - __bfloat162float(h01.x);
    float r1 = v.y - __bfloat162float(h01.y);
    float r2 = v.z - __bfloat162float(h23.x);
    float r3 = v.w - __bfloat162float(h23.y);
    __nv_bfloat162 l01 = __floats2bfloat162_rn(r0, r1);
    __nv_bfloat162 l23 = __floats2bfloat162_rn(r2, r3);
    hi = make_uint2(bf2_bits(h01), bf2_bits(h23));
    lo = make_uint2(bf2_bits(l01), bf2_bits(l23));
}
__device__ __forceinline__ int pick_idx(const float* logits, const float* u) {
    float best = -1e30f; int bi = 0;
    #pragma unroll
    for (int i = 0; i < NUM_OPS; i++) {
        float v = logits[i] - logf(-logf(u[i]));
        if (v > best) { best = v; bi = i; }
    }
    return bi;
}

__device__ __forceinline__ void ldsm_x4(uint32_t* r, uint32_t addr) {
    asm volatile("ldmatrix.sync.aligned.m8n8.x4.shared.b16 {%0,%1,%2,%3}, [%4];"
        : "=r"(r[0]), "=r"(r[1]), "=r"(r[2]), "=r"(r[3]) : "r"(addr));
}
__device__ __forceinline__ void mma_bf16(float* d, const uint32_t* a,
                                         const uint32_t* b) {
    asm volatile(
        "mma.sync.aligned.m16n8k16.row.col.f32.bf16.bf16.f32 "
        "{%0,%1,%2,%3}, {%4,%5,%6,%7}, {%8,%9}, {%0,%1,%2,%3};"
        : "+f"(d[0]), "+f"(d[1]), "+f"(d[2]), "+f"(d[3])
        : "r"(a[0]), "r"(a[1]), "r"(a[2]), "r"(a[3]), "r"(b[0]), "r"(b[1]));
}
__device__ __forceinline__ void cp16(uint32_t dst, const void* src) {
    asm volatile("cp.async.cg.shared.global [%0], [%1], 16;"
                 :: "r"(dst), "l"(src) : "memory");
}
#define CP_COMMIT() asm volatile("cp.async.commit_group;" ::: "memory")
#define CP_WAIT0()  asm volatile("cp.async.wait_group 0;" ::: "memory")

// ---------------- fused convert kernel ----------------
// blocks 0..255: transpose+split W[idx] 64x64 tiles -> g_Bh/g_Bl [N][K]
// blocks 256..511: elementwise split x -> g_Ah/g_Al
__global__ void __launch_bounds__(256)
convert_all_kernel(const float* __restrict__ x,
                   const float* __restrict__ W,
                   const float* __restrict__ logits,
                   const float* __restrict__ u) {
    const int tid = threadIdx.x;
    const int bid = blockIdx.x;

    if (bid < 256) {
        __shared__ float tile[64][65];
        const int idx = pick_idx(logits, u);
        const float* __restrict__ Wp = W + (size_t)idx * K_DIM * N_DIM;
        const int kbase = (bid >> 4) * 64;
        const int nbase = (bid & 15) * 64;

        #pragma unroll
        for (int p = 0; p < 4; p++) {
            int r = (tid >> 4) + p * 16;
            int c = (tid & 15) * 4;
            float4 v = *reinterpret_cast<const float4*>(
                Wp + (size_t)(kbase + r) * N_DIM + nbase + c);
            tile[r][c + 0] = v.x; tile[r][c + 1] = v.y;
            tile[r][c + 2] = v.z; tile[r][c + 3] = v.w;
        }
        __syncthreads();

        #pragma unroll
        for (int p = 0; p < 2; p++) {
            int n  = (tid >> 3) + p * 32;
            int k8 = (tid & 7) * 8;
            __nv_bfloat16 hv[8], lv[8];
            #pragma unroll
            for (int i = 0; i < 8; i++)
                split1(tile[k8 + i][n], hv[i], lv[i]);
            size_t off = (size_t)(nbase + n) * K_DIM + kbase + k8;
            *reinterpret_cast<uint4*>(&g_Bh[off]) = *reinterpret_cast<uint4*>(hv);
            *reinterpret_cast<uint4*>(&g_Bl[off]) = *reinterpret_cast<uint4*>(lv);
        }
    } else {
        const int n4 = M_DIM * K_DIM / 4;   // 1M float4
        for (int i = (bid - 256) * 256 + tid; i < n4; i += 256 * 256) {
            float4 v = reinterpret_cast<const float4*>(x)[i];
            uint2 hi, lo;
            split4(v, hi, lo);
            reinterpret_cast<uint2*>(g_Ah)[i] = hi;
            reinterpret_cast<uint2*>(g_Al)[i] = lo;
        }
    }
}

// ---------------- GEMM kernel ----------------
__global__ void __launch_bounds__(256, 2)
gemm_hmma_kernel(const float* __restrict__ b,
                 const float* __restrict__ logits,
                 const float* __restrict__ u,
                 float* __restrict__ out)
{
    extern __shared__ char smem[];
    const int tid = threadIdx.x;
    const int w = tid >> 5;          // 0..7
    const int l = tid & 31;

    const int idx = pick_idx(logits, u);
    const float* __restrict__ bp = b + idx * N_DIM;

    const int m0 = blockIdx.y * BM;
    const int n0 = blockIdx.x * BN;
    const uint32_t sb = (uint32_t)__cvta_generic_to_shared(smem);

    // warp tiling: 4 (m) x 2 (n); warp tile 32m x 64n
    const int warp_m = (w & 3) * 32;
    const int warp_n = (w >> 2) * 64;

    // cp.async coords: per tile 128 rows x 4 chunks(16B) = 512; 2/thread
    const int rc = tid >> 2;          // 0..63
    const int cc = tid & 3;

    auto load_stage = [&](int st, int k0) {
        const uint32_t stage = sb + st * STAGE_BYTES;
        #pragma unroll
        for (int j = 0; j < 2; j++) {
            const int r = rc + j * 64;
            const uint32_t doff = (uint32_t)(r * (PITCH * 2) + cc * 16);
            const size_t aoff = (size_t)(m0 + r) * K_DIM + k0 + cc * 8;
            const size_t boff = (size_t)(n0 + r) * K_DIM + k0 + cc * 8;
            cp16(stage + 0 * TILE_BYTES + doff, g_Ah + aoff);
            cp16(stage + 1 * TILE_BYTES + doff, g_Al + aoff);
            cp16(stage + 2 * TILE_BYTES + doff, g_Bh + boff);
            cp16(stage + 3 * TILE_BYTES + doff, g_Bl + boff);
        }
    };

    float acc[2][8][4] = {};   // [mi][nj][frag]

    // prologue
    load_stage(0, 0);
    CP_COMMIT();

    for (int s = 0; s < NSTEPS; s++) {
        CP_WAIT0();          // stage s data landed (only pending group)
        __syncthreads();     // all warps see it; also: all warps done with s-1
                             // -> buffer (s+1)&1 is free to overwrite
        if (s + 1 < NSTEPS) {
            load_stage((s + 1) & 1, (s + 1) * BK);
            CP_COMMIT();
        }

        const uint32_t stage = sb + (s & 1) * STAGE_BYTES;
        const uint32_t AhB = stage;
        const uint32_t AlB = stage + TILE_BYTES;
        const uint32_t BhB = stage + 2 * TILE_BYTES;
        const uint32_t BlB = stage + 3 * TILE_BYTES;

        #pragma unroll
        for (int ks = 0; ks < 2; ks++) {
            uint32_t afh[2][4], afl[2][4];
            #pragma unroll
            for (int mi = 0; mi < 2; mi++) {
                const uint32_t aoff =
                    (uint32_t)((warp_m + mi * 16 + (l & 15)) * (PITCH * 2) +
                               (ks * 16 + (l >> 4) * 8) * 2);
                ldsm_x4(afh[mi], AhB + aoff);
                ldsm_x4(afl[mi], AlB + aoff);
            }
            #pragma unroll
            for (int njp = 0; njp < 4; njp++) {
                uint32_t bfh[4], bfl[4];
                const uint32_t boff =
                    (uint32_t)((warp_n + njp * 16 + (l >> 4) * 8 + (l & 7)) *
                                   (PITCH * 2) +
                               (ks * 16 + ((l >> 3) & 1) * 8) * 2);
                ldsm_x4(bfh, BhB + boff);
                ldsm_x4(bfl, BlB + boff);

                #pragma unroll
                for (int mi = 0; mi < 2; mi++)
                    #pragma unroll
                    for (int h = 0; h < 2; h++) {
                        const int nj = njp * 2 + h;
                        mma_bf16(acc[mi][nj], afh[mi], &bfh[h * 2]);
                        mma_bf16(acc[mi][nj], afh[mi], &bfl[h * 2]);
                        mma_bf16(acc[mi][nj], afl[mi], &bfh[h * 2]);
                    }
            }
        }
        __syncthreads();     // all warps done with stage s before next overwrite
    }

    // epilogue: bias + store
    #pragma unroll
    for (int mi = 0; mi < 2; mi++) {
        const int r0 = m0 + warp_m + mi * 16 + (l >> 2);
        #pragma unroll
        for (int nj = 0; nj < 8; nj++) {
            const int col = n0 + warp_n + nj * 8 + (l & 3) * 2;
            const float b0 = __ldg(bp + col);
            const float b1 = __ldg(bp + col + 1);
            float2 v0 = make_float2(acc[mi][nj][0] + b0, acc[mi][nj][1] + b1);
            float2 v1 = make_float2(acc[mi][nj][2] + b0, acc[mi][nj][3] + b1);
            *reinterpret_cast<float2*>(out + (size_t)r0 * N_DIM + col) = v0;
            *reinterpret_cast<float2*>(out + (size_t)(r0 + 8) * N_DIM + col) = v1;
        }
    }
}

extern "C" void kernel_launch(void* const* d_in, const int* in_sizes, int n_in,
                              void* d_out, int out_size) {
    const float* x      = (const float*)d_in[0];  // [8,512,1024]
    const float* W      = (const float*)d_in[1];  // [8,1024,1024]
    const float* b      = (const float*)d_in[2];  // [8,1024]
    const float* logits = (const float*)d_in[3];  // [8]
    const float* u      = (const float*)d_in[4];  // [8]
    float* out          = (float*)d_out;          // [8,512,1024]

    convert_all_kernel<<<512, 256>>>(x, W, logits, u);

    cudaFuncSetAttribute(gemm_hmma_kernel,
                         cudaFuncAttributeMaxDynamicSharedMemorySize, SMEM_TOTAL);
    dim3 grid(N_DIM / BN, M_DIM / BM);  // (8, 32) = 256 CTAs, occ 2 -> 1 wave
    gemm_hmma_kernel<<<grid, 256, SMEM_TOTAL>>>(b, logits, u, out);
}

// round 13
// speedup vs baseline: 1.0406x; 1.0406x over previous
#include <cuda_runtime.h>
#include <cuda_bf16.h>
#include <cstdint>

#define M_DIM 4096
#define N_DIM 1024
#define K_DIM 1024
#define NUM_OPS 8

#define BM 128
#define BN 256
#define BK 32
#define NSTEPS (K_DIM / BK)   // 32
#define NSTAGE 3

// pitched rows: 40 bf16 = 80B = 5x16B (odd multiple -> conflict-free ldmatrix)
#define PITCH 40
#define A_TILE_BYTES (128 * PITCH * 2)        // 10240
#define B_TILE_BYTES (256 * PITCH * 2)        // 20480
#define STAGE_BYTES (2 * A_TILE_BYTES + 2 * B_TILE_BYTES)  // 61440
#define SMEM_TOTAL (NSTAGE * STAGE_BYTES)     // 184320

// ---- device scratch (pre-converted split operands) ----
__device__ __nv_bfloat16 g_Ah[M_DIM * K_DIM];   // [M][K]
__device__ __nv_bfloat16 g_Al[M_DIM * K_DIM];
__device__ __nv_bfloat16 g_Bh[N_DIM * K_DIM];   // [N][K] (W transposed)
__device__ __nv_bfloat16 g_Bl[N_DIM * K_DIM];

// ---------------- helpers ----------------
__device__ __forceinline__ uint32_t bf2_bits(__nv_bfloat162 h) {
    return *reinterpret_cast<uint32_t*>(&h);
}
__device__ __forceinline__ void split1(float v, __nv_bfloat16& hi, __nv_bfloat16& lo) {
    hi = __float2bfloat16_rn(v);
    lo = __float2bfloat16_rn(v - __bfloat162float(hi));
}
__device__ __forceinline__ void split4(float4 v, uint2& hi, uint2& lo) {
    __nv_bfloat162 h01 = __floats2bfloat162_rn(v.x, v.y);
    __nv_bfloat162 h23 = __floats2bfloat162_rn(v.z, v.w);
    float r0 = v.x - __bfloat162float(h01.x);
    float r1 = v.y - __bfloat162float(h01.y);
    float r2 = v.z - __bfloat162float(h23.x);
    float r3 = v.w - __bfloat162float(h23.y);
    __nv_bfloat162 l01 = __floats2bfloat162_rn(r0, r1);
    __nv_bfloat162 l23 = __floats2bfloat162_rn(r2, r3);
    hi = make_uint2(bf2_bits(h01), bf2_bits(h23));
    lo = make_uint2(bf2_bits(l01), bf2_bits(l23));
}
__device__ __forceinline__ int pick_idx(const float* logits, const float* u) {
    float best = -1e30f; int bi = 0;
    #pragma unroll
    for (int i = 0; i < NUM_OPS; i++) {
        float v = logits[i] - logf(-logf(u[i]));
        if (v > best) { best = v; bi = i; }
    }
    return bi;
}

__device__ __forceinline__ void ldsm_x4(uint32_t* r, uint32_t addr) {
    asm volatile("ldmatrix.sync.aligned.m8n8.x4.shared.b16 {%0,%1,%2,%3}, [%4];"
        : "=r"(r[0]), "=r"(r[1]), "=r"(r[2]), "=r"(r[3]) : "r"(addr));
}
__device__ __forceinline__ void mma_bf16(float* d, const uint32_t* a,
                                         const uint32_t* b) {
    asm volatile(
        "mma.sync.aligned.m16n8k16.row.col.f32.bf16.bf16.f32 "
        "{%0,%1,%2,%3}, {%4,%5,%6,%7}, {%8,%9}, {%0,%1,%2,%3};"
        : "+f"(d[0]), "+f"(d[1]), "+f"(d[2]), "+f"(d[3])
        : "r"(a[0]), "r"(a[1]), "r"(a[2]), "r"(a[3]), "r"(b[0]), "r"(b[1]));
}
__device__ __forceinline__ void cp16(uint32_t dst, const void* src) {
    asm volatile("cp.async.cg.shared.global [%0], [%1], 16;"
                 :: "r"(dst), "l"(src) : "memory");
}
#define CP_COMMIT() asm volatile("cp.async.commit_group;" ::: "memory")
#define CP_WAIT1()  asm volatile("cp.async.wait_group 1;" ::: "memory")

// ---------------- fused convert kernel ----------------
// blocks 0..255: transpose+split W[idx] 64x64 tiles -> g_Bh/g_Bl [N][K]
// blocks 256..511: elementwise split x -> g_Ah/g_Al
__global__ void __launch_bounds__(256)
convert_all_kernel(const float* __restrict__ x,
                   const float* __restrict__ W,
                   const float* __restrict__ logits,
                   const float* __restrict__ u) {
    const int tid = threadIdx.x;
    const int bid = blockIdx.x;

    if (bid < 256) {
        __shared__ float tile[64][65];
        const int idx = pick_idx(logits, u);
        const float* __restrict__ Wp = W + (size_t)idx * K_DIM * N_DIM;
        const int kbase = (bid >> 4) * 64;
        const int nbase = (bid & 15) * 64;

        #pragma unroll
        for (int p = 0; p < 4; p++) {
            int r = (tid >> 4) + p * 16;
            int c = (tid & 15) * 4;
            float4 v = *reinterpret_cast<const float4*>(
                Wp + (size_t)(kbase + r) * N_DIM + nbase + c);
            tile[r][c + 0] = v.x; tile[r][c + 1] = v.y;
            tile[r][c + 2] = v.z; tile[r][c + 3] = v.w;
        }
        __syncthreads();

        #pragma unroll
        for (int p = 0; p < 2; p++) {
            int n  = (tid >> 3) + p * 32;
            int k8 = (tid & 7) * 8;
            __nv_bfloat16 hv[8], lv[8];
            #pragma unroll
            for (int i = 0; i < 8; i++)
                split1(tile[k8 + i][n], hv[i], lv[i]);
            size_t off = (size_t)(nbase + n) * K_DIM + kbase + k8;
            *reinterpret_cast<uint4*>(&g_Bh[off]) = *reinterpret_cast<uint4*>(hv);
            *reinterpret_cast<uint4*>(&g_Bl[off]) = *reinterpret_cast<uint4*>(lv);
        }
    } else {
        const int n4 = M_DIM * K_DIM / 4;   // 1M float4
        for (int i = (bid - 256) * 256 + tid; i < n4; i += 256 * 256) {
            float4 v = reinterpret_cast<const float4*>(x)[i];
            uint2 hi, lo;
            split4(v, hi, lo);
            reinterpret_cast<uint2*>(g_Ah)[i] = hi;
            reinterpret_cast<uint2*>(g_Al)[i] = lo;
        }
    }
}

// ---------------- GEMM kernel ----------------
__global__ void __launch_bounds__(512, 1)
gemm_hmma_kernel(const float* __restrict__ b,
                 const float* __restrict__ logits,
                 const float* __restrict__ u,
                 float* __restrict__ out)
{
    extern __shared__ char smem[];
    const int tid = threadIdx.x;
    const int w = tid >> 5;          // 0..15
    const int l = tid & 31;

    const int idx = pick_idx(logits, u);
    const float* __restrict__ bp = b + idx * N_DIM;

    const int m0 = blockIdx.y * BM;
    const int n0 = blockIdx.x * BN;
    const uint32_t sb = (uint32_t)__cvta_generic_to_shared(smem);

    // warp tiling: 4 (m) x 4 (n); warp tile 32m x 64n
    const int warp_m = (w & 3) * 32;
    const int warp_n = (w >> 2) * 64;

    // cp.async coords
    const int rc = tid >> 2;          // 0..127
    const int cc = tid & 3;           // 16B chunk within 64B row

    auto load_stage = [&](int st, int k0) {
        const uint32_t stage = sb + st * STAGE_BYTES;
        const uint32_t AhS = stage;
        const uint32_t AlS = stage + A_TILE_BYTES;
        const uint32_t BhS = stage + 2 * A_TILE_BYTES;
        const uint32_t BlS = stage + 2 * A_TILE_BYTES + B_TILE_BYTES;

        {
            const uint32_t doff = (uint32_t)(rc * (PITCH * 2) + cc * 16);
            const size_t goff = (size_t)(m0 + rc) * K_DIM + k0 + cc * 8;
            cp16(AhS + doff, g_Ah + goff);
            cp16(AlS + doff, g_Al + goff);
        }
        #pragma unroll
        for (int j = 0; j < 2; j++) {
            const int r = rc + j * 128;
            const uint32_t doff = (uint32_t)(r * (PITCH * 2) + cc * 16);
            const size_t goff = (size_t)(n0 + r) * K_DIM + k0 + cc * 8;
            cp16(BhS + doff, g_Bh + goff);
            cp16(BlS + doff, g_Bl + goff);
        }
    };

    float acc[2][8][4] = {};   // [mi][nj][frag]

    // prologue: stages 0,1
    load_stage(0, 0);  CP_COMMIT();
    load_stage(1, BK); CP_COMMIT();

    int st = 0;
    for (int s = 0; s < NSTEPS; s++) {
        CP_WAIT1();          // group s complete
        __syncthreads();     // everyone done computing stage being overwritten

        if (s + 2 < NSTEPS) {
            int nst = st + 2; if (nst >= NSTAGE) nst -= NSTAGE;
            load_stage(nst, (s + 2) * BK);
        }
        CP_COMMIT();

        const uint32_t stage = sb + st * STAGE_BYTES;
        const uint32_t AhB = stage;
        const uint32_t AlB = stage + A_TILE_BYTES;
        const uint32_t BhB = stage + 2 * A_TILE_BYTES;
        const uint32_t BlB = stage + 2 * A_TILE_BYTES + B_TILE_BYTES;

        #pragma unroll
        for (int ks = 0; ks < 2; ks++) {
            uint32_t afh[2][4], afl[2][4];
            #pragma unroll
            for (int mi = 0; mi < 2; mi++) {
                const uint32_t aoff =
                    (uint32_t)((warp_m + mi * 16 + (l & 15)) * (PITCH * 2) +
                               (ks * 16 + (l >> 4) * 8) * 2);
                ldsm_x4(afh[mi], AhB + aoff);
                ldsm_x4(afl[mi], AlB + aoff);
            }
            #pragma unroll
            for (int njp = 0; njp < 4; njp++) {
                uint32_t bfh[4], bfl[4];
                const uint32_t boff =
                    (uint32_t)((warp_n + njp * 16 + (l >> 4) * 8 + (l & 7)) *
                                   (PITCH * 2) +
                               (ks * 16 + ((l >> 3) & 1) * 8) * 2);
                ldsm_x4(bfh, BhB + boff);
                ldsm_x4(bfl, BlB + boff);

                // term-outer ordering: 4 independent MMAs between any
                // dependent reuse of the same accumulator
                #pragma unroll
                for (int mi = 0; mi < 2; mi++)       // HH
                    #pragma unroll
                    for (int h = 0; h < 2; h++)
                        mma_bf16(acc[mi][njp * 2 + h], afh[mi], &bfh[h * 2]);
                #pragma unroll
                for (int mi = 0; mi < 2; mi++)       // HL
                    #pragma unroll
                    for (int h = 0; h < 2; h++)
                        mma_bf16(acc[mi][njp * 2 + h], afh[mi], &bfl[h * 2]);
                #pragma unroll
                for (int mi = 0; mi < 2; mi++)       // LH
                    #pragma unroll
                    for (int h = 0; h < 2; h++)
                        mma_bf16(acc[mi][njp * 2 + h], afl[mi], &bfh[h * 2]);
            }
        }

        if (++st == NSTAGE) st = 0;
    }

    // epilogue: bias + store
    #pragma unroll
    for (int mi = 0; mi < 2; mi++) {
        const int r0 = m0 + warp_m + mi * 16 + (l >> 2);
        #pragma unroll
        for (int nj = 0; nj < 8; nj++) {
            const int col = n0 + warp_n + nj * 8 + (l & 3) * 2;
            const float b0 = __ldg(bp + col);
            const float b1 = __ldg(bp + col + 1);
            float2 v0 = make_float2(acc[mi][nj][0] + b0, acc[mi][nj][1] + b1);
            float2 v1 = make_float2(acc[mi][nj][2] + b0, acc[mi][nj][3] + b1);
            *reinterpret_cast<float2*>(out + (size_t)r0 * N_DIM + col) = v0;
            *reinterpret_cast<float2*>(out + (size_t)(r0 + 8) * N_DIM + col) = v1;
        }
    }
}

extern "C" void kernel_launch(void* const* d_in, const int* in_sizes, int n_in,
                              void* d_out, int out_size) {
    const float* x      = (const float*)d_in[0];  // [8,512,1024]
    const float* W      = (const float*)d_in[1];  // [8,1024,1024]
    const float* b      = (const float*)d_in[2];  // [8,1024]
    const float* logits = (const float*)d_in[3];  // [8]
    const float* u      = (const float*)d_in[4];  // [8]
    float* out          = (float*)d_out;          // [8,512,1024]

    convert_all_kernel<<<512, 256>>>(x, W, logits, u);

    cudaFuncSetAttribute(gemm_hmma_kernel,
                         cudaFuncAttributeMaxDynamicSharedMemorySize, SMEM_TOTAL);
    dim3 grid(N_DIM / BN, M_DIM / BM);  // (4, 32) = 128 CTAs
    gemm_hmma_kernel<<<grid, 512, SMEM_TOTAL>>>(b, logits, u, out);
}

// round 14
// speedup vs baseline: 1.3883x; 1.3342x over previous
#include <cuda_runtime.h>
#include <cuda_fp16.h>
#include <cstdint>

#define M_DIM 4096
#define N_DIM 1024
#define K_DIM 1024
#define NUM_OPS 8

#define BM 128
#define BN 256
#define BK 32
#define NSTEPS (K_DIM / BK)   // 32
#define NSTAGE 4

// pitched rows: 40 fp16 = 80B = 5x16B (odd multiple -> conflict-free ldmatrix)
#define PITCH 40
#define A_TILE_BYTES (128 * PITCH * 2)        // 10240
#define B_TILE_BYTES (256 * PITCH * 2)        // 20480
#define STAGE_BYTES (2 * A_TILE_BYTES + B_TILE_BYTES)  // 40960 (Ah, Al, Bh)
#define SMEM_TOTAL (NSTAGE * STAGE_BYTES)     // 163840

// ---- device scratch (pre-converted operands) ----
__device__ __half g_Ah[M_DIM * K_DIM];   // [M][K] fp16 hi of x
__device__ __half g_Al[M_DIM * K_DIM];   // [M][K] fp16 lo of x
__device__ __half g_Bh[N_DIM * K_DIM];   // [N][K] fp16 of W[idx] (transposed)

// ---------------- helpers ----------------
__device__ __forceinline__ int pick_idx(const float* logits, const float* u) {
    float best = -1e30f; int bi = 0;
    #pragma unroll
    for (int i = 0; i < NUM_OPS; i++) {
        float v = logits[i] - logf(-logf(u[i]));
        if (v > best) { best = v; bi = i; }
    }
    return bi;
}

__device__ __forceinline__ void ldsm_x4(uint32_t* r, uint32_t addr) {
    asm volatile("ldmatrix.sync.aligned.m8n8.x4.shared.b16 {%0,%1,%2,%3}, [%4];"
        : "=r"(r[0]), "=r"(r[1]), "=r"(r[2]), "=r"(r[3]) : "r"(addr));
}
__device__ __forceinline__ void mma_fp16(float* d, const uint32_t* a,
                                         const uint32_t* b) {
    asm volatile(
        "mma.sync.aligned.m16n8k16.row.col.f32.f16.f16.f32 "
        "{%0,%1,%2,%3}, {%4,%5,%6,%7}, {%8,%9}, {%0,%1,%2,%3};"
        : "+f"(d[0]), "+f"(d[1]), "+f"(d[2]), "+f"(d[3])
        : "r"(a[0]), "r"(a[1]), "r"(a[2]), "r"(a[3]), "r"(b[0]), "r"(b[1]));
}
__device__ __forceinline__ void cp16(uint32_t dst, const void* src) {
    asm volatile("cp.async.cg.shared.global [%0], [%1], 16;"
                 :: "r"(dst), "l"(src) : "memory");
}
#define CP_COMMIT() asm volatile("cp.async.commit_group;" ::: "memory")
#define CP_WAIT2()  asm volatile("cp.async.wait_group 2;" ::: "memory")

// ---------------- fused convert kernel ----------------
// blocks 0..255: transpose W[idx] 64x64 tiles -> g_Bh [N][K] fp16
// blocks 256..511: split x -> g_Ah/g_Al fp16 hi/lo
__global__ void __launch_bounds__(256)
convert_all_kernel(const float* __restrict__ x,
                   const float* __restrict__ W,
                   const float* __restrict__ logits,
                   const float* __restrict__ u) {
    const int tid = threadIdx.x;
    const int bid = blockIdx.x;

    if (bid < 256) {
        __shared__ float tile[64][65];
        const int idx = pick_idx(logits, u);
        const float* __restrict__ Wp = W + (size_t)idx * K_DIM * N_DIM;
        const int kbase = (bid >> 4) * 64;
        const int nbase = (bid & 15) * 64;

        #pragma unroll
        for (int p = 0; p < 4; p++) {
            int r = (tid >> 4) + p * 16;
            int c = (tid & 15) * 4;
            float4 v = *reinterpret_cast<const float4*>(
                Wp + (size_t)(kbase + r) * N_DIM + nbase + c);
            tile[r][c + 0] = v.x; tile[r][c + 1] = v.y;
            tile[r][c + 2] = v.z; tile[r][c + 3] = v.w;
        }
        __syncthreads();

        #pragma unroll
        for (int p = 0; p < 2; p++) {
            int n  = (tid >> 3) + p * 32;
            int k8 = (tid & 7) * 8;
            __half hv[8];
            #pragma unroll
            for (int i = 0; i < 8; i++)
                hv[i] = __float2half_rn(tile[k8 + i][n]);
            size_t off = (size_t)(nbase + n) * K_DIM + kbase + k8;
            *reinterpret_cast<uint4*>(&g_Bh[off]) = *reinterpret_cast<uint4*>(hv);
        }
    } else {
        const int n4 = M_DIM * K_DIM / 4;   // 1M float4
        for (int i = (bid - 256) * 256 + tid; i < n4; i += 256 * 256) {
            float4 v = reinterpret_cast<const float4*>(x)[i];
            __half h[4], lo[4];
            h[0] = __float2half_rn(v.x); lo[0] = __float2half_rn(v.x - __half2float(h[0]));
            h[1] = __float2half_rn(v.y); lo[1] = __float2half_rn(v.y - __half2float(h[1]));
            h[2] = __float2half_rn(v.z); lo[2] = __float2half_rn(v.z - __half2float(h[2]));
            h[3] = __float2half_rn(v.w); lo[3] = __float2half_rn(v.w - __half2float(h[3]));
            reinterpret_cast<uint2*>(g_Ah)[i] = *reinterpret_cast<uint2*>(h);
            reinterpret_cast<uint2*>(g_Al)[i] = *reinterpret_cast<uint2*>(lo);
        }
    }
}

// ---------------- GEMM kernel ----------------
__global__ void __launch_bounds__(512, 1)
gemm_hmma_kernel(const float* __restrict__ b,
                 const float* __restrict__ logits,
                 const float* __restrict__ u,
                 float* __restrict__ out)
{
    extern __shared__ char smem[];
    const int tid = threadIdx.x;
    const int w = tid >> 5;          // 0..15
    const int l = tid & 31;

    const int idx = pick_idx(logits, u);
    const float* __restrict__ bp = b + idx * N_DIM;

    const int m0 = blockIdx.y * BM;
    const int n0 = blockIdx.x * BN;
    const uint32_t sb = (uint32_t)__cvta_generic_to_shared(smem);

    // warp tiling: 4 (m) x 4 (n); warp tile 32m x 64n
    const int warp_m = (w & 3) * 32;
    const int warp_n = (w >> 2) * 64;

    // cp.async coords: 2048 16B chunks per stage / 512 thr = 4 per thread
    const int rc = tid >> 2;          // 0..127
    const int cc = tid & 3;           // 16B chunk within 64B k-row

    auto load_stage = [&](int st, int k0) {
        const uint32_t stage = sb + st * STAGE_BYTES;
        const uint32_t AhS = stage;
        const uint32_t AlS = stage + A_TILE_BYTES;
        const uint32_t BhS = stage + 2 * A_TILE_BYTES;

        {
            const uint32_t doff = (uint32_t)(rc * (PITCH * 2) + cc * 16);
            const size_t goff = (size_t)(m0 + rc) * K_DIM + k0 + cc * 8;
            cp16(AhS + doff, g_Ah + goff);
            cp16(AlS + doff, g_Al + goff);
        }
        #pragma unroll
        for (int j = 0; j < 2; j++) {
            const int r = rc + j * 128;
            const uint32_t doff = (uint32_t)(r * (PITCH * 2) + cc * 16);
            const size_t goff = (size_t)(n0 + r) * K_DIM + k0 + cc * 8;
            cp16(BhS + doff, g_Bh + goff);
        }
    };

    float acc[2][8][4] = {};   // [mi][nj][frag]

    // prologue: stages 0..2
    load_stage(0, 0);      CP_COMMIT();
    load_stage(1, BK);     CP_COMMIT();
    load_stage(2, 2 * BK); CP_COMMIT();

    int st = 0;
    for (int s = 0; s < NSTEPS; s++) {
        CP_WAIT2();          // stage s landed (<=2 younger groups pending)
        __syncthreads();     // all warps done with stage (s-1)%4 (overwritten next)

        if (s + 3 < NSTEPS) {
            int nst = st + 3; if (nst >= NSTAGE) nst -= NSTAGE;
            load_stage(nst, (s + 3) * BK);
        }
        CP_COMMIT();

        const uint32_t stage = sb + st * STAGE_BYTES;
        const uint32_t AhB = stage;
        const uint32_t AlB = stage + A_TILE_BYTES;
        const uint32_t BhB = stage + 2 * A_TILE_BYTES;

        #pragma unroll
        for (int ks = 0; ks < 2; ks++) {
            uint32_t afh[2][4], afl[2][4];
            #pragma unroll
            for (int mi = 0; mi < 2; mi++) {
                const uint32_t aoff =
                    (uint32_t)((warp_m + mi * 16 + (l & 15)) * (PITCH * 2) +
                               (ks * 16 + (l >> 4) * 8) * 2);
                ldsm_x4(afh[mi], AhB + aoff);
                ldsm_x4(afl[mi], AlB + aoff);
            }
            #pragma unroll
            for (int njp = 0; njp < 4; njp++) {
                uint32_t bfh[4];
                const uint32_t boff =
                    (uint32_t)((warp_n + njp * 16 + (l >> 4) * 8 + (l & 7)) *
                                   (PITCH * 2) +
                               (ks * 16 + ((l >> 3) & 1) * 8) * 2);
                ldsm_x4(bfh, BhB + boff);

                // 4 independent MMAs between dependent accumulator reuses
                #pragma unroll
                for (int mi = 0; mi < 2; mi++)       // xh * Wh
                    #pragma unroll
                    for (int h = 0; h < 2; h++)
                        mma_fp16(acc[mi][njp * 2 + h], afh[mi], &bfh[h * 2]);
                #pragma unroll
                for (int mi = 0; mi < 2; mi++)       // xl * Wh
                    #pragma unroll
                    for (int h = 0; h < 2; h++)
                        mma_fp16(acc[mi][njp * 2 + h], afl[mi], &bfh[h * 2]);
            }
        }

        if (++st == NSTAGE) st = 0;
    }

    // epilogue: bias + store
    #pragma unroll
    for (int mi = 0; mi < 2; mi++) {
        const int r0 = m0 + warp_m + mi * 16 + (l >> 2);
        #pragma unroll
        for (int nj = 0; nj < 8; nj++) {
            const int col = n0 + warp_n + nj * 8 + (l & 3) * 2;
            const float b0 = __ldg(bp + col);
            const float b1 = __ldg(bp + col + 1);
            float2 v0 = make_float2(acc[mi][nj][0] + b0, acc[mi][nj][1] + b1);
            float2 v1 = make_float2(acc[mi][nj][2] + b0, acc[mi][nj][3] + b1);
            *reinterpret_cast<float2*>(out + (size_t)r0 * N_DIM + col) = v0;
            *reinterpret_cast<float2*>(out + (size_t)(r0 + 8) * N_DIM + col) = v1;
        }
    }
}

extern "C" void kernel_launch(void* const* d_in, const int* in_sizes, int n_in,
                              void* d_out, int out_size) {
    const float* x      = (const float*)d_in[0];  // [8,512,1024]
    const float* W      = (const float*)d_in[1];  // [8,1024,1024]
    const float* b      = (const float*)d_in[2];  // [8,1024]
    const float* logits = (const float*)d_in[3];  // [8]
    const float* u      = (const float*)d_in[4];  // [8]
    float* out          = (float*)d_out;          // [8,512,1024]

    convert_all_kernel<<<512, 256>>>(x, W, logits, u);

    cudaFuncSetAttribute(gemm_hmma_kernel,
                         cudaFuncAttributeMaxDynamicSharedMemorySize, SMEM_TOTAL);
    dim3 grid(N_DIM / BN, M_DIM / BM);  // (4, 32) = 128 CTAs
    gemm_hmma_kernel<<<grid, 512, SMEM_TOTAL>>>(b, logits, u, out);
}

// round 15
// speedup vs baseline: 2.0280x; 1.4608x over previous
#include <cuda_runtime.h>
#include <cuda_fp16.h>
#include <cstdint>

#define M_DIM 4096
#define N_DIM 1024
#define K_DIM 1024
#define NUM_OPS 8

#define BM 128
#define BN 256
#define BK 32
#define NSTEPS (K_DIM / BK)   // 32
#define NSTAGE 4

// pitched rows: 40 fp16 = 80B = 5x16B (odd multiple -> conflict-free ldmatrix)
#define PITCH 40
#define A_TILE_BYTES (128 * PITCH * 2)        // 10240
#define B_TILE_BYTES (256 * PITCH * 2)        // 20480
#define STAGE_BYTES (A_TILE_BYTES + B_TILE_BYTES)  // 30720 (Ah, Bh)
#define SMEM_TOTAL (NSTAGE * STAGE_BYTES)     // 122880

// ---- device scratch (pre-converted operands) ----
__device__ __half g_Ah[M_DIM * K_DIM];   // [M][K] fp16 of x
__device__ __half g_Bh[N_DIM * K_DIM];   // [N][K] fp16 of W[idx] (transposed)

// ---------------- helpers ----------------
__device__ __forceinline__ int pick_idx(const float* logits, const float* u) {
    float best = -1e30f; int bi = 0;
    #pragma unroll
    for (int i = 0; i < NUM_OPS; i++) {
        float v = logits[i] - logf(-logf(u[i]));
        if (v > best) { best = v; bi = i; }
    }
    return bi;
}

__device__ __forceinline__ void ldsm_x4(uint32_t* r, uint32_t addr) {
    asm volatile("ldmatrix.sync.aligned.m8n8.x4.shared.b16 {%0,%1,%2,%3}, [%4];"
        : "=r"(r[0]), "=r"(r[1]), "=r"(r[2]), "=r"(r[3]) : "r"(addr));
}
__device__ __forceinline__ void mma_fp16(float* d, const uint32_t* a,
                                         const uint32_t* b) {
    asm volatile(
        "mma.sync.aligned.m16n8k16.row.col.f32.f16.f16.f32 "
        "{%0,%1,%2,%3}, {%4,%5,%6,%7}, {%8,%9}, {%0,%1,%2,%3};"
        : "+f"(d[0]), "+f"(d[1]), "+f"(d[2]), "+f"(d[3])
        : "r"(a[0]), "r"(a[1]), "r"(a[2]), "r"(a[3]), "r"(b[0]), "r"(b[1]));
}
__device__ __forceinline__ void cp16(uint32_t dst, const void* src) {
    asm volatile("cp.async.cg.shared.global [%0], [%1], 16;"
                 :: "r"(dst), "l"(src) : "memory");
}
#define CP_COMMIT() asm volatile("cp.async.commit_group;" ::: "memory")
#define CP_WAIT2()  asm volatile("cp.async.wait_group 2;" ::: "memory")

// ---------------- fused convert kernel ----------------
// blocks 0..255: transpose W[idx] 64x64 tiles -> g_Bh [N][K] fp16
// blocks 256..511: round x -> g_Ah fp16
__global__ void __launch_bounds__(256)
convert_all_kernel(const float* __restrict__ x,
                   const float* __restrict__ W,
                   const float* __restrict__ logits,
                   const float* __restrict__ u) {
    const int tid = threadIdx.x;
    const int bid = blockIdx.x;

    if (bid < 256) {
        __shared__ float tile[64][65];
        const int idx = pick_idx(logits, u);
        const float* __restrict__ Wp = W + (size_t)idx * K_DIM * N_DIM;
        const int kbase = (bid >> 4) * 64;
        const int nbase = (bid & 15) * 64;

        #pragma unroll
        for (int p = 0; p < 4; p++) {
            int r = (tid >> 4) + p * 16;
            int c = (tid & 15) * 4;
            float4 v = *reinterpret_cast<const float4*>(
                Wp + (size_t)(kbase + r) * N_DIM + nbase + c);
            tile[r][c + 0] = v.x; tile[r][c + 1] = v.y;
            tile[r][c + 2] = v.z; tile[r][c + 3] = v.w;
        }
        __syncthreads();

        #pragma unroll
        for (int p = 0; p < 2; p++) {
            int n  = (tid >> 3) + p * 32;
            int k8 = (tid & 7) * 8;
            __half hv[8];
            #pragma unroll
            for (int i = 0; i < 8; i++)
                hv[i] = __float2half_rn(tile[k8 + i][n]);
            size_t off = (size_t)(nbase + n) * K_DIM + kbase + k8;
            *reinterpret_cast<uint4*>(&g_Bh[off]) = *reinterpret_cast<uint4*>(hv);
        }
    } else {
        const int n4 = M_DIM * K_DIM / 4;   // 1M float4
        for (int i = (bid - 256) * 256 + tid; i < n4; i += 256 * 256) {
            float4 v = reinterpret_cast<const float4*>(x)[i];
            __half h[4];
            h[0] = __float2half_rn(v.x);
            h[1] = __float2half_rn(v.y);
            h[2] = __float2half_rn(v.z);
            h[3] = __float2half_rn(v.w);
            reinterpret_cast<uint2*>(g_Ah)[i] = *reinterpret_cast<uint2*>(h);
        }
    }
}

// ---------------- GEMM kernel ----------------
__global__ void __launch_bounds__(512, 1)
gemm_hmma_kernel(const float* __restrict__ b,
                 const float* __restrict__ logits,
                 const float* __restrict__ u,
                 float* __restrict__ out)
{
    extern __shared__ char smem[];
    const int tid = threadIdx.x;
    const int w = tid >> 5;          // 0..15
    const int l = tid & 31;

    const int idx = pick_idx(logits, u);
    const float* __restrict__ bp = b + idx * N_DIM;

    const int m0 = blockIdx.y * BM;
    const int n0 = blockIdx.x * BN;
    const uint32_t sb = (uint32_t)__cvta_generic_to_shared(smem);

    // warp tiling: 4 (m) x 4 (n); warp tile 32m x 64n
    const int warp_m = (w & 3) * 32;
    const int warp_n = (w >> 2) * 64;

    // cp.async coords: 1536 16B chunks per stage / 512 thr = 3 per thread
    const int rc = tid >> 2;          // 0..127
    const int cc = tid & 3;           // 16B chunk within 64B k-row

    auto load_stage = [&](int st, int k0) {
        const uint32_t stage = sb + st * STAGE_BYTES;
        const uint32_t AhS = stage;
        const uint32_t BhS = stage + A_TILE_BYTES;

        {
            const uint32_t doff = (uint32_t)(rc * (PITCH * 2) + cc * 16);
            const size_t goff = (size_t)(m0 + rc) * K_DIM + k0 + cc * 8;
            cp16(AhS + doff, g_Ah + goff);
        }
        #pragma unroll
        for (int j = 0; j < 2; j++) {
            const int r = rc + j * 128;
            const uint32_t doff = (uint32_t)(r * (PITCH * 2) + cc * 16);
            const size_t goff = (size_t)(n0 + r) * K_DIM + k0 + cc * 8;
            cp16(BhS + doff, g_Bh + goff);
        }
    };

    float acc[2][8][4] = {};   // [mi][nj][frag]

    // prologue: stages 0..2
    load_stage(0, 0);      CP_COMMIT();
    load_stage(1, BK);     CP_COMMIT();
    load_stage(2, 2 * BK); CP_COMMIT();

    int st = 0;
    for (int s = 0; s < NSTEPS; s++) {
        CP_WAIT2();          // stage s landed (<=2 younger groups pending)
        __syncthreads();     // all warps done with stage (s-1)%4 (overwritten next)

        if (s + 3 < NSTEPS) {
            int nst = st + 3; if (nst >= NSTAGE) nst -= NSTAGE;
            load_stage(nst, (s + 3) * BK);
        }
        CP_COMMIT();

        const uint32_t stage = sb + st * STAGE_BYTES;
        const uint32_t AhB = stage;
        const uint32_t BhB = stage + A_TILE_BYTES;

        #pragma unroll
        for (int ks = 0; ks < 2; ks++) {
            uint32_t afh[2][4];
            #pragma unroll
            for (int mi = 0; mi < 2; mi++) {
                const uint32_t aoff =
                    (uint32_t)((warp_m + mi * 16 + (l & 15)) * (PITCH * 2) +
                               (ks * 16 + (l >> 4) * 8) * 2);
                ldsm_x4(afh[mi], AhB + aoff);
            }
            #pragma unroll
            for (int njp = 0; njp < 4; njp++) {
                uint32_t bfh[4];
                const uint32_t boff =
                    (uint32_t)((warp_n + njp * 16 + (l >> 4) * 8 + (l & 7)) *
                                   (PITCH * 2) +
                               (ks * 16 + ((l >> 3) & 1) * 8) * 2);
                ldsm_x4(bfh, BhB + boff);

                #pragma unroll
                for (int mi = 0; mi < 2; mi++)
                    #pragma unroll
                    for (int h = 0; h < 2; h++)
                        mma_fp16(acc[mi][njp * 2 + h], afh[mi], &bfh[h * 2]);
            }
        }

        if (++st == NSTAGE) st = 0;
    }

    // epilogue: bias + store
    #pragma unroll
    for (int mi = 0; mi < 2; mi++) {
        const int r0 = m0 + warp_m + mi * 16 + (l >> 2);
        #pragma unroll
        for (int nj = 0; nj < 8; nj++) {
            const int col = n0 + warp_n + nj * 8 + (l & 3) * 2;
            const float b0 = __ldg(bp + col);
            const float b1 = __ldg(bp + col + 1);
            float2 v0 = make_float2(acc[mi][nj][0] + b0, acc[mi][nj][1] + b1);
            float2 v1 = make_float2(acc[mi][nj][2] + b0, acc[mi][nj][3] + b1);
            *reinterpret_cast<float2*>(out + (size_t)r0 * N_DIM + col) = v0;
            *reinterpret_cast<float2*>(out + (size_t)(r0 + 8) * N_DIM + col) = v1;
        }
    }
}

extern "C" void kernel_launch(void* const* d_in, const int* in_sizes, int n_in,
                              void* d_out, int out_size) {
    const float* x      = (const float*)d_in[0];  // [8,512,1024]
    const float* W      = (const float*)d_in[1];  // [8,1024,1024]
    const float* b      = (const float*)d_in[2];  // [8,1024]
    const float* logits = (const float*)d_in[3];  // [8]
    const float* u      = (const float*)d_in[4];  // [8]
    float* out          = (float*)d_out;          // [8,512,1024]

    convert_all_kernel<<<512, 256>>>(x, W, logits, u);

    cudaFuncSetAttribute(gemm_hmma_kernel,
                         cudaFuncAttributeMaxDynamicSharedMemorySize, SMEM_TOTAL);
    dim3 grid(N_DIM / BN, M_DIM / BM);  // (4, 32) = 128 CTAs
    gemm_hmma_kernel<<<grid, 512, SMEM_TOTAL>>>(b, logits, u, out);
}

// round 16
// speedup vs baseline: 2.4194x; 1.1930x over previous
#include <cuda_runtime.h>
#include <cuda_fp16.h>
#include <cstdint>

#define M_DIM 4096
#define N_DIM 1024
#define K_DIM 1024
#define NUM_OPS 8

#define BM 128
#define BN 256
#define BK 64
#define NSTEPS (K_DIM / BK)   // 16
#define NSTAGE 2

// pitched rows: 72 fp16 = 144B = 9 x 16B (odd multiple -> conflict-free ldmatrix)
#define PITCH 72
#define A_TILE_BYTES (128 * PITCH * 2)        // 18432
#define B_TILE_BYTES (256 * PITCH * 2)        // 36864
#define STAGE_BYTES (A_TILE_BYTES + B_TILE_BYTES)  // 55296
#define SMEM_TOTAL (NSTAGE * STAGE_BYTES)     // 110592

// ---- device scratch (pre-converted operands) ----
__device__ __half g_Ah[M_DIM * K_DIM];   // [M][K] fp16 of x
__device__ __half g_Bh[N_DIM * K_DIM];   // [N][K] fp16 of W[idx] (transposed)

// ---------------- helpers ----------------
__device__ __forceinline__ int pick_idx(const float* logits, const float* u) {
    float best = -1e30f; int bi = 0;
    #pragma unroll
    for (int i = 0; i < NUM_OPS; i++) {
        float v = logits[i] - logf(-logf(u[i]));
        if (v > best) { best = v; bi = i; }
    }
    return bi;
}

__device__ __forceinline__ void ldsm_x4(uint32_t* r, uint32_t addr) {
    asm volatile("ldmatrix.sync.aligned.m8n8.x4.shared.b16 {%0,%1,%2,%3}, [%4];"
        : "=r"(r[0]), "=r"(r[1]), "=r"(r[2]), "=r"(r[3]) : "r"(addr));
}
__device__ __forceinline__ void mma_fp16(float* d, const uint32_t* a,
                                         const uint32_t* b) {
    asm volatile(
        "mma.sync.aligned.m16n8k16.row.col.f32.f16.f16.f32 "
        "{%0,%1,%2,%3}, {%4,%5,%6,%7}, {%8,%9}, {%0,%1,%2,%3};"
        : "+f"(d[0]), "+f"(d[1]), "+f"(d[2]), "+f"(d[3])
        : "r"(a[0]), "r"(a[1]), "r"(a[2]), "r"(a[3]), "r"(b[0]), "r"(b[1]));
}
__device__ __forceinline__ void cp16(uint32_t dst, const void* src) {
    asm volatile("cp.async.cg.shared.global [%0], [%1], 16;"
                 :: "r"(dst), "l"(src) : "memory");
}
#define CP_COMMIT() asm volatile("cp.async.commit_group;" ::: "memory")
#define CP_WAIT0()  asm volatile("cp.async.wait_group 0;" ::: "memory")

// ---------------- fused convert kernel ----------------
// blocks 0..255: transpose W[idx] 64x64 tiles -> g_Bh [N][K] fp16
// blocks 256..511: round x -> g_Ah fp16
__global__ void __launch_bounds__(256)
convert_all_kernel(const float* __restrict__ x,
                   const float* __restrict__ W,
                   const float* __restrict__ logits,
                   const float* __restrict__ u) {
    const int tid = threadIdx.x;
    const int bid = blockIdx.x;

    if (bid < 256) {
        __shared__ float tile[64][65];
        const int idx = pick_idx(logits, u);
        const float* __restrict__ Wp = W + (size_t)idx * K_DIM * N_DIM;
        const int kbase = (bid >> 4) * 64;
        const int nbase = (bid & 15) * 64;

        #pragma unroll
        for (int p = 0; p < 4; p++) {
            int r = (tid >> 4) + p * 16;
            int c = (tid & 15) * 4;
            float4 v = *reinterpret_cast<const float4*>(
                Wp + (size_t)(kbase + r) * N_DIM + nbase + c);
            tile[r][c + 0] = v.x; tile[r][c + 1] = v.y;
            tile[r][c + 2] = v.z; tile[r][c + 3] = v.w;
        }
        __syncthreads();

        #pragma unroll
        for (int p = 0; p < 2; p++) {
            int n  = (tid >> 3) + p * 32;
            int k8 = (tid & 7) * 8;
            __half hv[8];
            #pragma unroll
            for (int i = 0; i < 8; i++)
                hv[i] = __float2half_rn(tile[k8 + i][n]);
            size_t off = (size_t)(nbase + n) * K_DIM + kbase + k8;
            *reinterpret_cast<uint4*>(&g_Bh[off]) = *reinterpret_cast<uint4*>(hv);
        }
    } else {
        const int n4 = M_DIM * K_DIM / 4;   // 1M float4
        for (int i = (bid - 256) * 256 + tid; i < n4; i += 256 * 256) {
            float4 v = reinterpret_cast<const float4*>(x)[i];
            __half h[4];
            h[0] = __float2half_rn(v.x);
            h[1] = __float2half_rn(v.y);
            h[2] = __float2half_rn(v.z);
            h[3] = __float2half_rn(v.w);
            reinterpret_cast<uint2*>(g_Ah)[i] = *reinterpret_cast<uint2*>(h);
        }
    }
}

// ---------------- GEMM kernel ----------------
__global__ void __launch_bounds__(512, 1)
gemm_hmma_kernel(const float* __restrict__ b,
                 const float* __restrict__ logits,
                 const float* __restrict__ u,
                 float* __restrict__ out)
{
    extern __shared__ char smem[];
    const int tid = threadIdx.x;
    const int w = tid >> 5;          // 0..15
    const int l = tid & 31;

    const int idx = pick_idx(logits, u);
    const float* __restrict__ bp = b + idx * N_DIM;

    const int m0 = blockIdx.y * BM;
    const int n0 = blockIdx.x * BN;
    const uint32_t sb = (uint32_t)__cvta_generic_to_shared(smem);

    // warp tiling: 4 (m) x 4 (n); warp tile 32m x 64n
    const int warp_m = (w & 3) * 32;
    const int warp_n = (w >> 2) * 64;

    // cp.async coords: rows of 128B = 8 x 16B chunks
    const int rc = tid >> 3;          // 0..63
    const int cc = tid & 7;           // chunk within 128B k-row

    auto load_stage = [&](int st, int k0) {
        const uint32_t stage = sb + st * STAGE_BYTES;
        const uint32_t AhS = stage;
        const uint32_t BhS = stage + A_TILE_BYTES;

        // A: 128 rows x 8 chunks = 1024 -> 2 per thread
        #pragma unroll
        for (int j = 0; j < 2; j++) {
            const int r = rc + j * 64;
            const uint32_t doff = (uint32_t)(r * (PITCH * 2) + cc * 16);
            const size_t goff = (size_t)(m0 + r) * K_DIM + k0 + cc * 8;
            cp16(AhS + doff, g_Ah + goff);
        }
        // B: 256 rows x 8 chunks = 2048 -> 4 per thread
        #pragma unroll
        for (int j = 0; j < 4; j++) {
            const int r = rc + j * 64;
            const uint32_t doff = (uint32_t)(r * (PITCH * 2) + cc * 16);
            const size_t goff = (size_t)(n0 + r) * K_DIM + k0 + cc * 8;
            cp16(BhS + doff, g_Bh + goff);
        }
    };

    float acc[2][8][4] = {};   // [mi][nj][frag]

    // prologue: stage 0
    load_stage(0, 0);
    CP_COMMIT();

    for (int s = 0; s < NSTEPS; s++) {
        CP_WAIT0();          // stage s landed (only pending group)
        __syncthreads();     // all warps see it; all done with stage s-1
                             // -> buffer (s+1)&1 free to overwrite
        if (s + 1 < NSTEPS) {
            load_stage((s + 1) & 1, (s + 1) * BK);
            CP_COMMIT();
        }

        const uint32_t stage = sb + (s & 1) * STAGE_BYTES;
        const uint32_t AhB = stage;
        const uint32_t BhB = stage + A_TILE_BYTES;

        #pragma unroll
        for (int ks = 0; ks < 4; ks++) {
            uint32_t afh[2][4];
            #pragma unroll
            for (int mi = 0; mi < 2; mi++) {
                const uint32_t aoff =
                    (uint32_t)((warp_m + mi * 16 + (l & 15)) * (PITCH * 2) +
                               (ks * 16 + (l >> 4) * 8) * 2);
                ldsm_x4(afh[mi], AhB + aoff);
            }
            #pragma unroll
            for (int njp = 0; njp < 4; njp++) {
                uint32_t bfh[4];
                const uint32_t boff =
                    (uint32_t)((warp_n + njp * 16 + (l >> 4) * 8 + (l & 7)) *
                                   (PITCH * 2) +
                               (ks * 16 + ((l >> 3) & 1) * 8) * 2);
                ldsm_x4(bfh, BhB + boff);

                #pragma unroll
                for (int mi = 0; mi < 2; mi++)
                    #pragma unroll
                    for (int h = 0; h < 2; h++)
                        mma_fp16(acc[mi][njp * 2 + h], afh[mi], &bfh[h * 2]);
            }
        }
    }

    // epilogue: bias + store
    #pragma unroll
    for (int mi = 0; mi < 2; mi++) {
        const int r0 = m0 + warp_m + mi * 16 + (l >> 2);
        #pragma unroll
        for (int nj = 0; nj < 8; nj++) {
            const int col = n0 + warp_n + nj * 8 + (l & 3) * 2;
            const float b0 = __ldg(bp + col);
            const float b1 = __ldg(bp + col + 1);
            float2 v0 = make_float2(acc[mi][nj][0] + b0, acc[mi][nj][1] + b1);
            float2 v1 = make_float2(acc[mi][nj][2] + b0, acc[mi][nj][3] + b1);
            *reinterpret_cast<float2*>(out + (size_t)r0 * N_DIM + col) = v0;
            *reinterpret_cast<float2*>(out + (size_t)(r0 + 8) * N_DIM + col) = v1;
        }
    }
}

extern "C" void kernel_launch(void* const* d_in, const int* in_sizes, int n_in,
                              void* d_out, int out_size) {
    const float* x      = (const float*)d_in[0];  // [8,512,1024]
    const float* W      = (const float*)d_in[1];  // [8,1024,1024]
    const float* b      = (const float*)d_in[2];  // [8,1024]
    const float* logits = (const float*)d_in[3];  // [8]
    const float* u      = (const float*)d_in[4];  // [8]
    float* out          = (float*)d_out;          // [8,512,1024]

    convert_all_kernel<<<512, 256>>>(x, W, logits, u);

    cudaFuncSetAttribute(gemm_hmma_kernel,
                         cudaFuncAttributeMaxDynamicSharedMemorySize, SMEM_TOTAL);
    dim3 grid(N_DIM / BN, M_DIM / BM);  // (4, 32) = 128 CTAs
    gemm_hmma_kernel<<<grid, 512, SMEM_TOTAL>>>(b, logits, u, out);
}